// round 9
// baseline (speedup 1.0000x reference)
#include <cuda_runtime.h>

#define IMG_H 256
#define IMG_W 256
#define KS    33
#define PADV  16
#define TX    32
#define TY    8
#define VEC   4                      // pixels per thread (float4 weight loads)
#define TILE_W (TX * VEC)            // 128
#define PW2   (TILE_W + KS - 1)      // 160 patch width
#define PLANE (IMG_H * IMG_W)        // 65536

#define GROUPS  11
#define FH_PER  3                    // 33 = 11 * 3, exact
#define NTAPS   (FH_PER * KS)        // 99 taps per group, linear in memory
#define PH_SUB  (TY - 1 + FH_PER)    // 10 patch rows per group
#define PF      8                    // explicit LDG.128 pipeline depth

__global__ void zero_out_kernel(float* __restrict__ out)
{
    int i = blockIdx.x * blockDim.x + threadIdx.x;
    ((float4*)out)[i] = make_float4(0.f, 0.f, 0.f, 0.f);
}

__global__ __launch_bounds__(TX * TY, 4)
void reblur_dynconv_pf_kernel(const float* __restrict__ img,
                              const float* __restrict__ ker,
                              float* __restrict__ out)
{
    __shared__ float s0[PH_SUB * PW2];
    __shared__ float s1[PH_SUB * PW2];
    __shared__ float s2[PH_SUB * PW2];

    const int lx  = threadIdx.x;
    const int ly  = threadIdx.y;
    const int tid = ly * TX + lx;
    const int bx0 = blockIdx.x * TILE_W;
    const int by0 = blockIdx.y * TY;
    const int f0  = blockIdx.z * FH_PER;          // first fh row of this group

    // Cooperative load of the replication-padded sub-patch:
    // rows [by0 + f0 - PAD, +PH_SUB), cols [bx0 - PAD, +PW2), 3 channels.
    for (int i = tid; i < PH_SUB * PW2; i += TX * TY) {
        const int py = i / PW2;
        const int px = i - py * PW2;
        int gy = by0 + f0 + py - PADV;
        int gx = bx0 + px - PADV;
        gy = gy < 0 ? 0 : (gy > IMG_H - 1 ? IMG_H - 1 : gy);
        gx = gx < 0 ? 0 : (gx > IMG_W - 1 ? IMG_W - 1 : gx);
        const int gi = gy * IMG_W + gx;
        s0[i] = img[gi];
        s1[i] = img[PLANE + gi];
        s2[i] = img[2 * PLANE + gi];
    }
    __syncthreads();

    const int x0  = bx0 + lx * VEC;               // first of 4 consecutive pixels
    const int y   = by0 + ly;
    const int pix = y * IMG_W + x0;
    // Weight pointer for tap (f0, 0) at pixel x0. Tap t (= fh*33 + fw within
    // this group) lives at kp + t*PLANE — LINEAR across fh-row boundaries.
    const float* __restrict__ kp = ker + (size_t)f0 * KS * PLANE + pix;

    float a00 = 0.f, a01 = 0.f, a02 = 0.f, a03 = 0.f;   // channel 0, px 0..3
    float a10 = 0.f, a11 = 0.f, a12 = 0.f, a13 = 0.f;   // channel 1
    float a20 = 0.f, a21 = 0.f, a22 = 0.f, a23 = 0.f;   // channel 2

    // Explicit rotating prefetch buffer: PF LDG.128 always in flight.
    float4 wb[PF];
    #pragma unroll
    for (int p = 0; p < PF; ++p)
        wb[p] = *(const float4*)&kp[(size_t)p * PLANE];

    #pragma unroll 1
    for (int fh = 0; fh < FH_PER; ++fh) {
        const float* __restrict__ r0 = &s0[(ly + fh) * PW2 + lx * VEC];
        const float* __restrict__ r1 = &s1[(ly + fh) * PW2 + lx * VEC];
        const float* __restrict__ r2 = &s2[(ly + fh) * PW2 + lx * VEC];
        const float* __restrict__ kr = kp + (size_t)fh * KS * PLANE;
        const int tbase = fh * KS;

        #pragma unroll
        for (int fw = 0; fw < KS; ++fw) {
            float4 w = wb[(tbase + fw) & (PF - 1) ? (tbase + fw) % PF : 0];
            // NOTE: slot index must be compile-time-foldable; use % PF directly
            w = wb[(tbase + fw) % PF];

            // Prefetch tap t+PF (rolls into next fh row automatically since
            // the tap stride is uniform). Predicated off for the final PF taps
            // of the group to avoid reading past the last kernel plane.
            if (tbase + fw + PF < NTAPS)
                wb[(tbase + fw) % PF] = *(const float4*)&kr[(size_t)(fw + PF) * PLANE];

            w.x = (w.x > 1e-4f) ? w.x : 0.0f;
            w.y = (w.y > 1e-4f) ? w.y : 0.0f;
            w.z = (w.z > 1e-4f) ? w.z : 0.0f;
            w.w = (w.w > 1e-4f) ? w.w : 0.0f;

            a00 = fmaf(w.x, r0[fw    ], a00);
            a01 = fmaf(w.y, r0[fw + 1], a01);
            a02 = fmaf(w.z, r0[fw + 2], a02);
            a03 = fmaf(w.w, r0[fw + 3], a03);

            a10 = fmaf(w.x, r1[fw    ], a10);
            a11 = fmaf(w.y, r1[fw + 1], a11);
            a12 = fmaf(w.z, r1[fw + 2], a12);
            a13 = fmaf(w.w, r1[fw + 3], a13);

            a20 = fmaf(w.x, r2[fw    ], a20);
            a21 = fmaf(w.y, r2[fw + 1], a21);
            a22 = fmaf(w.z, r2[fw + 2], a22);
            a23 = fmaf(w.w, r2[fw + 3], a23);
        }
    }

    atomicAdd(&out[pix    ], a00);
    atomicAdd(&out[pix + 1], a01);
    atomicAdd(&out[pix + 2], a02);
    atomicAdd(&out[pix + 3], a03);

    atomicAdd(&out[PLANE + pix    ], a10);
    atomicAdd(&out[PLANE + pix + 1], a11);
    atomicAdd(&out[PLANE + pix + 2], a12);
    atomicAdd(&out[PLANE + pix + 3], a13);

    atomicAdd(&out[2 * PLANE + pix    ], a20);
    atomicAdd(&out[2 * PLANE + pix + 1], a21);
    atomicAdd(&out[2 * PLANE + pix + 2], a22);
    atomicAdd(&out[2 * PLANE + pix + 3], a23);
}

extern "C" void kernel_launch(void* const* d_in, const int* in_sizes, int n_in,
                              void* d_out, int out_size)
{
    const float* img = (const float*)d_in[0];   // [1,3,256,256]
    const float* ker = (const float*)d_in[1];   // [1,1089,256,256]
    float* out = (float*)d_out;                 // [1,3,256,256]

    zero_out_kernel<<<(3 * PLANE / 4) / 256, 256>>>(out);

    dim3 block(TX, TY);
    dim3 grid(IMG_W / TILE_W, IMG_H / TY, GROUPS);  // 2 x 32 x 11 = 704 CTAs
    reblur_dynconv_pf_kernel<<<grid, block>>>(img, ker, out);
}

// round 10
// speedup vs baseline: 2.2857x; 2.2857x over previous
#include <cuda_runtime.h>

#define IMG_H 256
#define IMG_W 256
#define KS    33
#define PADV  16
#define TX    32
#define TY    8
#define VEC   4                      // pixels per thread
#define TILE_W (TX * VEC)            // 128
#define PW2   (TILE_W + KS - 1)      // 160 patch width
#define PLANE (IMG_H * IMG_W)        // 65536

#define GROUPS  11
#define FH_PER  3                    // 33 = 11 * 3, exact
#define NTAPS   (FH_PER * KS)        // 99 taps per group, linear planes
#define PH_SUB  (TY - 1 + FH_PER)    // 10 patch rows per group

#define DRING     4                  // smem ring depth (taps in flight per warp)
#define SLOT_F    (TILE_W)           // 128 floats (512 B) per tap per warp

__device__ __forceinline__ unsigned smem_u32(const void* p)
{
    return (unsigned)__cvta_generic_to_shared(p);
}
#define CP_ASYNC16(dst_u32, src_gen) \
    asm volatile("cp.async.cg.shared.global [%0], [%1], 16;\n" :: "r"(dst_u32), "l"(src_gen))
#define CP_COMMIT() asm volatile("cp.async.commit_group;\n" ::: "memory")
#define CP_WAIT3()  asm volatile("cp.async.wait_group 3;\n" ::: "memory")

__global__ void zero_out_kernel(float* __restrict__ out)
{
    int i = blockIdx.x * blockDim.x + threadIdx.x;
    ((float4*)out)[i] = make_float4(0.f, 0.f, 0.f, 0.f);
}

__global__ __launch_bounds__(TX * TY)
void reblur_dynconv_cp_kernel(const float* __restrict__ img,
                              const float* __restrict__ ker,
                              float* __restrict__ out)
{
    __shared__ float s0[PH_SUB * PW2];
    __shared__ float s1[PH_SUB * PW2];
    __shared__ float s2[PH_SUB * PW2];
    __shared__ __align__(16) float wring[TY * DRING * SLOT_F];  // 16 KB

    const int lx  = threadIdx.x;
    const int ly  = threadIdx.y;        // == warp id (TY warps of TX lanes)
    const int tid = ly * TX + lx;
    const int bx0 = blockIdx.x * TILE_W;
    const int by0 = blockIdx.y * TY;
    const int f0  = blockIdx.z * FH_PER;

    const int x0  = bx0 + lx * VEC;
    const int y   = by0 + ly;
    const int pix = y * IMG_W + x0;

    // Per-warp weight stream base: tap t of this group lives at kw + t*PLANE,
    // lane lx covers 16 bytes at +lx*4 floats. Linear across fh rows.
    const float* __restrict__ kw = ker + (size_t)(f0 * KS) * PLANE + pix;

    // Per-warp ring base (u32 shared address), lane-fixed 16B slot.
    const unsigned ring = smem_u32(&wring[ly * (DRING * SLOT_F)]) + lx * 16;

    // Prologue: start taps 0..DRING-1 streaming before patch staging.
    #pragma unroll
    for (int p = 0; p < DRING; ++p) {
        CP_ASYNC16(ring + p * (SLOT_F * 4), kw + (size_t)p * PLANE);
        CP_COMMIT();
    }

    // Cooperative load of the replication-padded sub-patch (3 channels).
    for (int i = tid; i < PH_SUB * PW2; i += TX * TY) {
        const int py = i / PW2;
        const int px = i - py * PW2;
        int gy = by0 + f0 + py - PADV;
        int gx = bx0 + px - PADV;
        gy = gy < 0 ? 0 : (gy > IMG_H - 1 ? IMG_H - 1 : gy);
        gx = gx < 0 ? 0 : (gx > IMG_W - 1 ? IMG_W - 1 : gx);
        const int gi = gy * IMG_W + gx;
        s0[i] = img[gi];
        s1[i] = img[PLANE + gi];
        s2[i] = img[2 * PLANE + gi];
    }
    __syncthreads();

    float a00 = 0.f, a01 = 0.f, a02 = 0.f, a03 = 0.f;
    float a10 = 0.f, a11 = 0.f, a12 = 0.f, a13 = 0.f;
    float a20 = 0.f, a21 = 0.f, a22 = 0.f, a23 = 0.f;

    #pragma unroll 1
    for (int fh = 0; fh < FH_PER; ++fh) {
        const float* __restrict__ r0 = &s0[(ly + fh) * PW2 + lx * VEC];
        const float* __restrict__ r1 = &s1[(ly + fh) * PW2 + lx * VEC];
        const float* __restrict__ r2 = &s2[(ly + fh) * PW2 + lx * VEC];
        const int tbase = fh * KS;

        #pragma unroll
        for (int fw = 0; fw < KS; ++fw) {
            const int t    = tbase + fw;
            const unsigned slot = ring + (unsigned)((t & (DRING - 1)) * (SLOT_F * 4));

            CP_WAIT3();                     // tap t has landed in its slot
            float4 w = *(const float4*)__cvta_shared_to_generic(slot);

            // Refill this slot with tap t+DRING (same ring position), then
            // always commit to keep the group count aligned with t.
            const int tn = t + DRING;
            if (tn < NTAPS)
                CP_ASYNC16(slot, kw + (size_t)tn * PLANE);
            CP_COMMIT();

            w.x = (w.x > 1e-4f) ? w.x : 0.0f;
            w.y = (w.y > 1e-4f) ? w.y : 0.0f;
            w.z = (w.z > 1e-4f) ? w.z : 0.0f;
            w.w = (w.w > 1e-4f) ? w.w : 0.0f;

            a00 = fmaf(w.x, r0[fw    ], a00);
            a01 = fmaf(w.y, r0[fw + 1], a01);
            a02 = fmaf(w.z, r0[fw + 2], a02);
            a03 = fmaf(w.w, r0[fw + 3], a03);

            a10 = fmaf(w.x, r1[fw    ], a10);
            a11 = fmaf(w.y, r1[fw + 1], a11);
            a12 = fmaf(w.z, r1[fw + 2], a12);
            a13 = fmaf(w.w, r1[fw + 3], a13);

            a20 = fmaf(w.x, r2[fw    ], a20);
            a21 = fmaf(w.y, r2[fw + 1], a21);
            a22 = fmaf(w.z, r2[fw + 2], a22);
            a23 = fmaf(w.w, r2[fw + 3], a23);
        }
    }

    atomicAdd(&out[pix    ], a00);
    atomicAdd(&out[pix + 1], a01);
    atomicAdd(&out[pix + 2], a02);
    atomicAdd(&out[pix + 3], a03);

    atomicAdd(&out[PLANE + pix    ], a10);
    atomicAdd(&out[PLANE + pix + 1], a11);
    atomicAdd(&out[PLANE + pix + 2], a12);
    atomicAdd(&out[PLANE + pix + 3], a13);

    atomicAdd(&out[2 * PLANE + pix    ], a20);
    atomicAdd(&out[2 * PLANE + pix + 1], a21);
    atomicAdd(&out[2 * PLANE + pix + 2], a22);
    atomicAdd(&out[2 * PLANE + pix + 3], a23);
}

extern "C" void kernel_launch(void* const* d_in, const int* in_sizes, int n_in,
                              void* d_out, int out_size)
{
    const float* img = (const float*)d_in[0];   // [1,3,256,256]
    const float* ker = (const float*)d_in[1];   // [1,1089,256,256]
    float* out = (float*)d_out;                 // [1,3,256,256]

    zero_out_kernel<<<(3 * PLANE / 4) / 256, 256>>>(out);

    dim3 block(TX, TY);
    dim3 grid(IMG_W / TILE_W, IMG_H / TY, GROUPS);  // 2 x 32 x 11 = 704 CTAs
    reblur_dynconv_cp_kernel<<<grid, block>>>(img, ker, out);
}

// round 12
// speedup vs baseline: 2.7699x; 1.2118x over previous
#include <cuda_runtime.h>

#define IMG_H 256
#define IMG_W 256
#define KS    33
#define PADV  16
#define TX    32
#define TY    8
#define VEC   4                      // pixels per thread (float4 weight loads)
#define TILE_W (TX * VEC)            // 128
#define PW2   (TILE_W + KS - 1)      // 160 patch width
#define PLANE (IMG_H * IMG_W)        // 65536

#define CHUNK  11                    // taps per explicit load batch (33 = 3*11)
#define PH_SUB TY                    // fh fixed per CTA -> 8 patch rows only

__global__ void zero_out_kernel(float* __restrict__ out)
{
    int i = blockIdx.x * blockDim.x + threadIdx.x;
    ((float4*)out)[i] = make_float4(0.f, 0.f, 0.f, 0.f);
}

__global__ __launch_bounds__(TX * TY)
void reblur_dynconv_batch_kernel(const float* __restrict__ img,
                                 const float* __restrict__ ker,
                                 float* __restrict__ out)
{
    __shared__ float s0[PH_SUB * PW2];
    __shared__ float s1[PH_SUB * PW2];
    __shared__ float s2[PH_SUB * PW2];

    const int lx  = threadIdx.x;
    const int ly  = threadIdx.y;
    const int tid = ly * TX + lx;
    const int bx0 = blockIdx.x * TILE_W;
    const int by0 = blockIdx.y * TY;
    const int fh  = blockIdx.z;              // single kernel row per CTA

    // Stage the replication-padded patch rows [by0+fh-PAD, +8) x [bx0-PAD, +160),
    // 3 channels. Image is 768KB -> these re-reads all hit L2.
    for (int i = tid; i < PH_SUB * PW2; i += TX * TY) {
        const int py = i / PW2;
        const int px = i - py * PW2;
        int gy = by0 + fh + py - PADV;
        int gx = bx0 + px - PADV;
        gy = gy < 0 ? 0 : (gy > IMG_H - 1 ? IMG_H - 1 : gy);
        gx = gx < 0 ? 0 : (gx > IMG_W - 1 ? IMG_W - 1 : gx);
        const int gi = gy * IMG_W + gx;
        s0[i] = img[gi];
        s1[i] = img[PLANE + gi];
        s2[i] = img[2 * PLANE + gi];
    }
    __syncthreads();

    const int x0  = bx0 + lx * VEC;
    const int y   = by0 + ly;
    const int pix = y * IMG_W + x0;
    // Weights for taps (fh, fw): planes fh*33 + fw, fw = 0..32.
    const float* __restrict__ kr = ker + (size_t)(fh * KS) * PLANE + pix;

    // fh fixed -> each thread only touches its own smem row.
    const float* __restrict__ r0 = &s0[ly * PW2 + lx * VEC];
    const float* __restrict__ r1 = &s1[ly * PW2 + lx * VEC];
    const float* __restrict__ r2 = &s2[ly * PW2 + lx * VEC];

    float a00 = 0.f, a01 = 0.f, a02 = 0.f, a03 = 0.f;
    float a10 = 0.f, a11 = 0.f, a12 = 0.f, a13 = 0.f;
    float a20 = 0.f, a21 = 0.f, a22 = 0.f, a23 = 0.f;

    // 3 batches of 11 taps: issue 11 straight-line LDG.128 (44 regs live),
    // then consume. No rotating indices, no reg cap -> no spill; ptxas can
    // overlap batch c+1 loads with batch c FMAs.
    #pragma unroll
    for (int c = 0; c < KS / CHUNK; ++c) {
        float4 w[CHUNK];
        #pragma unroll
        for (int j = 0; j < CHUNK; ++j)
            w[j] = *(const float4*)&kr[(size_t)(c * CHUNK + j) * PLANE];

        #pragma unroll
        for (int j = 0; j < CHUNK; ++j) {
            const int fw = c * CHUNK + j;
            float4 v = w[j];
            v.x = (v.x > 1e-4f) ? v.x : 0.0f;
            v.y = (v.y > 1e-4f) ? v.y : 0.0f;
            v.z = (v.z > 1e-4f) ? v.z : 0.0f;
            v.w = (v.w > 1e-4f) ? v.w : 0.0f;

            a00 = fmaf(v.x, r0[fw    ], a00);
            a01 = fmaf(v.y, r0[fw + 1], a01);
            a02 = fmaf(v.z, r0[fw + 2], a02);
            a03 = fmaf(v.w, r0[fw + 3], a03);

            a10 = fmaf(v.x, r1[fw    ], a10);
            a11 = fmaf(v.y, r1[fw + 1], a11);
            a12 = fmaf(v.z, r1[fw + 2], a12);
            a13 = fmaf(v.w, r1[fw + 3], a13);

            a20 = fmaf(v.x, r2[fw    ], a20);
            a21 = fmaf(v.y, r2[fw + 1], a21);
            a22 = fmaf(v.z, r2[fw + 2], a22);
            a23 = fmaf(v.w, r2[fw + 3], a23);
        }
    }

    atomicAdd(&out[pix    ], a00);
    atomicAdd(&out[pix + 1], a01);
    atomicAdd(&out[pix + 2], a02);
    atomicAdd(&out[pix + 3], a03);

    atomicAdd(&out[PLANE + pix    ], a10);
    atomicAdd(&out[PLANE + pix + 1], a11);
    atomicAdd(&out[PLANE + pix + 2], a12);
    atomicAdd(&out[PLANE + pix + 3], a13);

    atomicAdd(&out[2 * PLANE + pix    ], a20);
    atomicAdd(&out[2 * PLANE + pix + 1], a21);
    atomicAdd(&out[2 * PLANE + pix + 2], a22);
    atomicAdd(&out[2 * PLANE + pix + 3], a23);
}

extern "C" void kernel_launch(void* const* d_in, const int* in_sizes, int n_in,
                              void* d_out, int out_size)
{
    const float* img = (const float*)d_in[0];   // [1,3,256,256]
    const float* ker = (const float*)d_in[1];   // [1,1089,256,256]
    float* out = (float*)d_out;                 // [1,3,256,256]

    zero_out_kernel<<<(3 * PLANE / 4) / 256, 256>>>(out);

    dim3 block(TX, TY);
    dim3 grid(IMG_W / TILE_W, IMG_H / TY, KS);  // 2 x 32 x 33 = 2112 CTAs
    reblur_dynconv_batch_kernel<<<grid, block>>>(img, ker, out);
}